// round 15
// baseline (speedup 1.0000x reference)
#include <cuda_runtime.h>
#include <cstdint>

#define NF     12
#define NPAIR  66
#define NCOMB  781
#define NCOLS  793
#define NROWS  32768
#define WPB    8            // warps per block
#define RPW    2            // rows per warp (per unit)
#define NUNITS (NROWS / RPW)   // 16384 two-row work units
#define NBLK   1184         // 148 SMs x 8 blocks: one fully-resident wave
#define NVAL   80           // slots: 0..11 s_i, 12..77 pairs, 78 = 1.0, pad

// pair id, lexicographic i<j
constexpr int pid(int i, int j) { return i * (2 * NF - i - 1) / 2 + (j - i - 1); }

// ---------------------------------------------------------------------------
// Combo table: two 16-bit BYTE offsets into val[NVAL][2] (8 B per slot).
// combo value p = val[a] * val[b]; q = 1 - p via FFMA with negate modifier.
// ---------------------------------------------------------------------------
struct CTbl { uint32_t v[NCOMB]; };
struct PTbl { uint32_t v[NPAIR]; };

constexpr CTbl make_ctbl() {
    CTbl t{};
    int p = 0;
    for (int i = 0; i < NF; ++i)                    // size 2: P2 * 1
        for (int j = i + 1; j < NF; ++j)
            t.v[p++] = (uint32_t)((12 + pid(i, j)) * 8)
                     | ((uint32_t)(78 * 8) << 16);
    for (int i = 0; i < NF; ++i)                    // size 3: P2(i,j) * s_k
        for (int j = i + 1; j < NF; ++j)
            for (int k = j + 1; k < NF; ++k)
                t.v[p++] = (uint32_t)((12 + pid(i, j)) * 8)
                         | ((uint32_t)(k * 8) << 16);
    for (int i = 0; i < NF; ++i)                    // size 4: P2(i,j) * P2(k,l)
        for (int j = i + 1; j < NF; ++j)
            for (int k = j + 1; k < NF; ++k)
                for (int l = k + 1; l < NF; ++l)
                    t.v[p++] = (uint32_t)((12 + pid(i, j)) * 8)
                             | ((uint32_t)((12 + pid(k, l)) * 8) << 16);
    return t;
}
constexpr PTbl make_ptbl() {
    PTbl t{};
    int p = 0;
    for (int i = 0; i < NF; ++i)
        for (int j = i + 1; j < NF; ++j)
            t.v[p++] = (uint32_t)i | ((uint32_t)j << 8);
    return t;
}

__device__ const CTbl d_ct = make_ctbl();
__device__ const PTbl d_pt = make_ptbl();

__device__ unsigned g_ctr;            // work-unit counter

__device__ __forceinline__ float lg2a(float x) {
    float r; asm("lg2.approx.f32 %0,%1;" : "=f"(r) : "f"(x)); return r;
}
__device__ __forceinline__ float ex2a(float x) {
    float r; asm("ex2.approx.f32 %0,%1;" : "=f"(r) : "f"(x)); return r;
}
__device__ __forceinline__ float ss(float a, float b, float inv) {
    // 1 - (1 - a*b)^inv ; FFMA negate modifier makes the -a free
    return 1.0f - ex2a(lg2a(fmaf(-a, b, 1.0f)) * inv);
}

__global__ void reset_kernel() { g_ctr = 0u; }

// ---------------------------------------------------------------------------
// Persistent blocks, per-warp atomic stealing of 2-row units. Body identical
// to the proven R12 kernel (LDS.64 dual-row operands, FFMA-negate, streaming
// stores, fully unrolled 24-group sweep).
// ---------------------------------------------------------------------------
__global__ __launch_bounds__(256)
void schweizer_kernel(const float* __restrict__ x,
                      const float* __restrict__ lam_p,
                      float* __restrict__ out)
{
    __shared__ __align__(8) float val[WPB][NVAL][RPW];

    const int lane = threadIdx.x & 31;
    const int wrp  = threadIdx.x >> 5;

    const float lam = __ldg(lam_p);
    const float inv = 1.0f / lam;

    float (*v)[RPW] = val[wrp];
    const char* vb = (const char*)v;

    for (;;) {
        // ---- steal next 2-row unit -----------------------------------------
        unsigned u;
        if (lane == 0) u = atomicAdd(&g_ctr, 1u);
        u = __shfl_sync(0xFFFFFFFFu, u, 0);
        if (u >= NUNITS) break;
        const int r0 = (int)u * RPW;

        // ---- prologue: s_i for 2 rows + passthrough -------------------------
        if (lane < RPW * NF) {
            const float xv = __ldg(x + (size_t)r0 * NF + lane);
            const int f = lane % NF, r = lane / NF;
            v[f][r] = 1.0f - ex2a(lg2a(1.0f - xv) * lam);
            __stcs(out + (size_t)(r0 + r) * NCOLS + f, xv);
        } else if (lane < RPW * NF + RPW) {
            v[78][lane - RPW * NF] = 1.0f;                   // sentinel
        }
        __syncwarp();

        // ---- 66 pairwise products (vectorized over 2 rows) ------------------
        #pragma unroll
        for (int p = lane; p < NPAIR; p += 32) {
            const uint32_t w = __ldg(&d_pt.v[p]);
            const float2 a = *(const float2*)v[w & 0xFFu];
            const float2 b = *(const float2*)v[w >> 8];
            float2 r2;
            r2.x = a.x * b.x;
            r2.y = a.y * b.y;
            *(float2*)v[12 + p] = r2;
        }
        __syncwarp();

        // ---- main sweep: 24 full 32-column groups, fully unrolled ------------
        float* __restrict__ o0 = out + (size_t)r0 * NCOLS + NF;
        float* __restrict__ o1 = o0 + NCOLS;

        #pragma unroll
        for (int k = 0; k < 24; ++k) {
            const int c = k * 32 + lane;
            const uint32_t w = __ldg(&d_ct.v[c]);
            const float2 a = *(const float2*)(vb + (w & 0xFFFFu));
            const float2 b = *(const float2*)(vb + (w >> 16));
            __stcs(o0 + c, ss(a.x, b.x, inv));
            __stcs(o1 + c, ss(a.y, b.y, inv));
        }
        if (lane < NCOMB - 768) {                            // cols 768..780
            const int c = 768 + lane;
            const uint32_t w = __ldg(&d_ct.v[c]);
            const float2 a = *(const float2*)(vb + (w & 0xFFFFu));
            const float2 b = *(const float2*)(vb + (w >> 16));
            __stcs(o0 + c, ss(a.x, b.x, inv));
            __stcs(o1 + c, ss(a.y, b.y, inv));
        }
        __syncwarp();
    }
}

extern "C" void kernel_launch(void* const* d_in, const int* in_sizes, int n_in,
                              void* d_out, int out_size)
{
    const float* x   = (const float*)d_in[0];
    const float* lam = (const float*)d_in[1];
    float*       out = (float*)d_out;

    reset_kernel<<<1, 1>>>();
    schweizer_kernel<<<NBLK, 256>>>(x, lam, out);
}

// round 16
// speedup vs baseline: 1.5160x; 1.5160x over previous
#include <cuda_runtime.h>
#include <cstdint>

#define NF     12
#define NPAIR  66
#define NCOMB  781
#define NCOLS  793
#define NROWS  32768
#define WPB    8            // warps per block
#define RPW    2            // rows per warp
#define NGRP   25           // 25 uniform groups of 32 cols (last overlaps)
#define NVAL   96           // slots: 0..11 s_i, 12 = 1.0, 16..95 pair slots
#define ONE_SLOT 12

constexpr int pid(int i, int j) { return i * (2 * NF - i - 1) / 2 + (j - i - 1); }

// ---------------------------------------------------------------------------
// Compile-time bank-aware build:
//  - pair products get slots chosen by a greedy that balances conflict
//    classes (slot mod 16) across the distinct addresses of every group
//  - combo table: two 16-bit byte offsets per column (a = pair, b = s/one/pair)
//  - pair table: i | j<<8 | dest_byte_off<<16
// ---------------------------------------------------------------------------
struct Build {
    uint32_t ct[NGRP * 32];
    uint32_t pt[NPAIR];
};

constexpr Build make_build() {
    // enumerate combos: A = pair id, B kind: 0..11 = s_k, 12 = one, 16+q = pair q
    int aPair[NCOMB] = {}, bKind[NCOMB] = {};
    int idx = 0;
    for (int i = 0; i < NF; ++i) for (int j = i + 1; j < NF; ++j)
        { aPair[idx] = pid(i, j); bKind[idx] = ONE_SLOT; ++idx; }
    for (int i = 0; i < NF; ++i) for (int j = i + 1; j < NF; ++j)
        for (int k = j + 1; k < NF; ++k)
            { aPair[idx] = pid(i, j); bKind[idx] = k; ++idx; }
    for (int i = 0; i < NF; ++i) for (int j = i + 1; j < NF; ++j)
        for (int k = j + 1; k < NF; ++k) for (int l = k + 1; l < NF; ++l)
            { aPair[idx] = pid(i, j); bKind[idx] = 16 + pid(k, l); ++idx; }

    // distinct (pair, group) reference bits; groups: c/32 for c<768, plus
    // group 24 covering cols 749..780
    bool refBit[NPAIR][NGRP] = {};
    int  usage[NPAIR] = {};
    for (int c = 0; c < NCOMB; ++c) {
        int qa = aPair[c];
        if (c < 768)          refBit[qa][c / 32] = true;
        if (c >= NCOMB - 32)  refBit[qa][24] = true;
        if (bKind[c] >= 16) {
            int qb = bKind[c] - 16;
            if (c < 768)         refBit[qb][c / 32] = true;
            if (c >= NCOMB - 32) refBit[qb][24] = true;
        }
        usage[qa]++;
        if (bKind[c] >= 16) usage[bKind[c] - 16]++;
    }

    // per-group class load, seeded with the fixed s/one slots (distinct)
    int gcnt[NGRP][16] = {};
    {
        bool seen[NGRP][13] = {};
        for (int c = 0; c < NCOMB; ++c) {
            int b = bKind[c];
            if (b < 16) {
                if (c < 768 && !seen[c / 32][b]) { seen[c / 32][b] = true; gcnt[c / 32][b]++; }
                if (c >= NCOMB - 32 && !seen[24][b]) { seen[24][b] = true; gcnt[24][b]++; }
            }
        }
    }

    // order pairs by usage desc (selection)
    int order[NPAIR] = {};
    bool taken[NPAIR] = {};
    for (int o = 0; o < NPAIR; ++o) {
        int best = -1;
        for (int q = 0; q < NPAIR; ++q)
            if (!taken[q] && (best < 0 || usage[q] > usage[best])) best = q;
        taken[best] = true; order[o] = best;
    }

    // greedy class assignment
    int cls[NPAIR] = {};
    int clsFill[16] = {};
    for (int o = 0; o < NPAIR; ++o) {
        const int q = order[o];
        long bestCost = (long)1 << 40; int bestC = 0;
        for (int cc = 0; cc < 16; ++cc) {
            if (clsFill[cc] >= 5) continue;             // 5 slots per class max
            long cost = 0;
            for (int g = 0; g < NGRP; ++g)
                if (refBit[q][g]) cost += gcnt[g][cc];
            if (cost < bestCost) { bestCost = cost; bestC = cc; }
        }
        cls[q] = bestC;
        clsFill[bestC]++;
        for (int g = 0; g < NGRP; ++g)
            if (refBit[q][g]) gcnt[g][bestC]++;
    }

    // slot per pair: class c occupies slots 16+c, 32+c, 48+c, 64+c, 80+c
    int slot[NPAIR] = {};
    {
        int nth[16] = {};
        for (int o = 0; o < NPAIR; ++o) {
            const int q = order[o];
            slot[q] = 16 + cls[q] + 16 * nth[cls[q]];
            nth[cls[q]]++;
        }
    }

    Build B{};
    {
        int p = 0;
        for (int i = 0; i < NF; ++i)
            for (int j = i + 1; j < NF; ++j) {
                B.pt[p] = (uint32_t)i | ((uint32_t)j << 8)
                        | ((uint32_t)(slot[p] * 8) << 16);
                ++p;
            }
    }
    for (int g = 0; g < NGRP; ++g)
        for (int l = 0; l < 32; ++l) {
            const int c = (g < 24) ? g * 32 + l : (NCOMB - 32 + l);
            const int aoff = slot[aPair[c]] * 8;
            const int b = bKind[c];
            const int boff = (b < 16) ? b * 8 : slot[b - 16] * 8;
            B.ct[g * 32 + l] = (uint32_t)aoff | ((uint32_t)boff << 16);
        }
    return B;
}

__device__ const Build d_b = make_build();

__device__ __forceinline__ float lg2a(float x) {
    float r; asm("lg2.approx.f32 %0,%1;" : "=f"(r) : "f"(x)); return r;
}
__device__ __forceinline__ float ex2a(float x) {
    float r; asm("ex2.approx.f32 %0,%1;" : "=f"(r) : "f"(x)); return r;
}
__device__ __forceinline__ float ss(float a, float b, float inv) {
    return 1.0f - ex2a(lg2a(fmaf(-a, b, 1.0f)) * inv);
}

// ---------------------------------------------------------------------------
// R12 body + bank-aware slots + uniform 25-group sweep.
// ---------------------------------------------------------------------------
__global__ __launch_bounds__(256)
void schweizer_kernel(const float* __restrict__ x,
                      const float* __restrict__ lam_p,
                      float* __restrict__ out)
{
    __shared__ __align__(8) float val[WPB][NVAL][RPW];

    const int lane = threadIdx.x & 31;
    const int wrp  = threadIdx.x >> 5;
    const int r0   = (blockIdx.x * WPB + wrp) * RPW;

    const float lam = __ldg(lam_p);
    const float inv = 1.0f / lam;

    float (*v)[RPW] = val[wrp];
    char* vb = (char*)v;

    // ---- prologue: s_i for 2 rows + passthrough ----------------------------
    if (lane < RPW * NF) {
        const float xv = __ldg(x + (size_t)r0 * NF + lane);
        const int f = lane % NF, r = lane / NF;
        v[f][r] = 1.0f - ex2a(lg2a(1.0f - xv) * lam);
        __stcs(out + (size_t)(r0 + r) * NCOLS + f, xv);
    } else if (lane < RPW * NF + RPW) {
        v[ONE_SLOT][lane - RPW * NF] = 1.0f;             // sentinel
    }
    __syncwarp();

    // ---- 66 pairwise products into bank-balanced slots ---------------------
    #pragma unroll
    for (int p = lane; p < NPAIR; p += 32) {
        const uint32_t w = __ldg(&d_b.pt[p]);
        const float2 a = *(const float2*)v[w & 0xFFu];
        const float2 b = *(const float2*)v[(w >> 8) & 0xFFu];
        float2 r2;
        r2.x = a.x * b.x;
        r2.y = a.y * b.y;
        *(float2*)(vb + (w >> 16)) = r2;
    }
    __syncwarp();

    // ---- main sweep: 25 uniform 32-column groups ----------------------------
    float* __restrict__ o0 = out + (size_t)r0 * NCOLS + NF;
    float* __restrict__ o1 = o0 + NCOLS;

    #pragma unroll
    for (int g = 0; g < NGRP; ++g) {
        const int c = (g < 24) ? g * 32 + lane : (NCOMB - 32 + lane);
        const uint32_t w = __ldg(&d_b.ct[g * 32 + lane]);
        const float2 a = *(const float2*)(vb + (w & 0xFFFFu));
        const float2 b = *(const float2*)(vb + (w >> 16));
        __stcs(o0 + c, ss(a.x, b.x, inv));
        __stcs(o1 + c, ss(a.y, b.y, inv));
    }
}

extern "C" void kernel_launch(void* const* d_in, const int* in_sizes, int n_in,
                              void* d_out, int out_size)
{
    const float* x   = (const float*)d_in[0];
    const float* lam = (const float*)d_in[1];
    float*       out = (float*)d_out;

    schweizer_kernel<<<NROWS / (WPB * RPW), 256>>>(x, lam, out);
}

// round 17
// speedup vs baseline: 1.5417x; 1.0170x over previous
#include <cuda_runtime.h>
#include <cstdint>

#define NF     12
#define NPAIR  66
#define NCOMB  781
#define NCOLS  793
#define NROWS  32768
#define WPB    8            // warps per block
#define RPW    2            // rows per warp
#define NVAL   80           // slots: 0..11 s_i, 12..77 pairs, 78 = 1.0, pad

// pair id, lexicographic i<j
constexpr int pid(int i, int j) { return i * (2 * NF - i - 1) / 2 + (j - i - 1); }

// ---------------------------------------------------------------------------
// Combo table: two 16-bit BYTE offsets into val[NVAL][2] (8 B per slot).
// combo value p = val[a] * val[b]; q = 1 - p via FFMA with negate modifier.
// ---------------------------------------------------------------------------
struct CTbl { uint32_t v[NCOMB]; };
struct PTbl { uint32_t v[NPAIR]; };

constexpr CTbl make_ctbl() {
    CTbl t{};
    int p = 0;
    for (int i = 0; i < NF; ++i)                    // size 2: P2 * 1
        for (int j = i + 1; j < NF; ++j)
            t.v[p++] = (uint32_t)((12 + pid(i, j)) * 8)
                     | ((uint32_t)(78 * 8) << 16);
    for (int i = 0; i < NF; ++i)                    // size 3: P2(i,j) * s_k
        for (int j = i + 1; j < NF; ++j)
            for (int k = j + 1; k < NF; ++k)
                t.v[p++] = (uint32_t)((12 + pid(i, j)) * 8)
                         | ((uint32_t)(k * 8) << 16);
    for (int i = 0; i < NF; ++i)                    // size 4: P2(i,j) * P2(k,l)
        for (int j = i + 1; j < NF; ++j)
            for (int k = j + 1; k < NF; ++k)
                for (int l = k + 1; l < NF; ++l)
                    t.v[p++] = (uint32_t)((12 + pid(i, j)) * 8)
                             | ((uint32_t)((12 + pid(k, l)) * 8) << 16);
    return t;
}
constexpr PTbl make_ptbl() {
    PTbl t{};
    int p = 0;
    for (int i = 0; i < NF; ++i)
        for (int j = i + 1; j < NF; ++j)
            t.v[p++] = (uint32_t)i | ((uint32_t)j << 8);
    return t;
}

__device__ const CTbl d_ct = make_ctbl();
__device__ const PTbl d_pt = make_ptbl();

__device__ __forceinline__ float lg2a(float x) {
    float r; asm("lg2.approx.f32 %0,%1;" : "=f"(r) : "f"(x)); return r;
}
__device__ __forceinline__ float ex2a(float x) {
    float r; asm("ex2.approx.f32 %0,%1;" : "=f"(r) : "f"(x)); return r;
}

// ---------------------------------------------------------------------------
// R12 body with 2-group column interleave: each sweep iteration carries
// 4 independent LDS->FFMA->LG2->FMUL->EX2->FADD chains (2 cols x 2 rows),
// doubling in-warp latency hiding without touching the prologue.
// ---------------------------------------------------------------------------
__global__ __launch_bounds__(256)
void schweizer_kernel(const float* __restrict__ x,
                      const float* __restrict__ lam_p,
                      float* __restrict__ out)
{
    __shared__ __align__(8) float val[WPB][NVAL][RPW];

    const int lane = threadIdx.x & 31;
    const int wrp  = threadIdx.x >> 5;
    const int r0   = (blockIdx.x * WPB + wrp) * RPW;

    const float lam = __ldg(lam_p);
    const float inv = 1.0f / lam;

    float (*v)[RPW] = val[wrp];
    const char* vb = (const char*)v;

    // ---- prologue: s_i for 2 rows + passthrough ----------------------------
    if (lane < RPW * NF) {
        const float xv = __ldg(x + (size_t)r0 * NF + lane);
        const int f = lane % NF, r = lane / NF;
        v[f][r] = 1.0f - ex2a(lg2a(1.0f - xv) * lam);
        __stcs(out + (size_t)(r0 + r) * NCOLS + f, xv);
    } else if (lane < RPW * NF + RPW) {
        v[78][lane - RPW * NF] = 1.0f;                   // sentinel
    }
    __syncwarp();

    // ---- 66 pairwise products (vectorized over 2 rows) ---------------------
    #pragma unroll
    for (int p = lane; p < NPAIR; p += 32) {
        const uint32_t w = __ldg(&d_pt.v[p]);
        const float2 a = *(const float2*)v[w & 0xFFu];
        const float2 b = *(const float2*)v[w >> 8];
        float2 r2;
        r2.x = a.x * b.x;
        r2.y = a.y * b.y;
        *(float2*)v[12 + p] = r2;
    }
    __syncwarp();

    // ---- main sweep: 12 iterations x 2 interleaved 32-column groups ---------
    float* __restrict__ o0 = out + (size_t)r0 * NCOLS + NF;
    float* __restrict__ o1 = o0 + NCOLS;

    #pragma unroll
    for (int gp = 0; gp < 12; ++gp) {
        const int c0 = (2 * gp) * 32 + lane;
        const int c1 = c0 + 32;
        const uint32_t w0 = __ldg(&d_ct.v[c0]);
        const uint32_t w1 = __ldg(&d_ct.v[c1]);
        const float2 aA = *(const float2*)(vb + (w0 & 0xFFFFu));
        const float2 bA = *(const float2*)(vb + (w0 >> 16));
        const float2 aB = *(const float2*)(vb + (w1 & 0xFFFFu));
        const float2 bB = *(const float2*)(vb + (w1 >> 16));
        // 4 independent chains
        const float qA0 = fmaf(-aA.x, bA.x, 1.0f);
        const float qA1 = fmaf(-aA.y, bA.y, 1.0f);
        const float qB0 = fmaf(-aB.x, bB.x, 1.0f);
        const float qB1 = fmaf(-aB.y, bB.y, 1.0f);
        const float lA0 = lg2a(qA0) * inv;
        const float lA1 = lg2a(qA1) * inv;
        const float lB0 = lg2a(qB0) * inv;
        const float lB1 = lg2a(qB1) * inv;
        __stcs(o0 + c0, 1.0f - ex2a(lA0));
        __stcs(o1 + c0, 1.0f - ex2a(lA1));
        __stcs(o0 + c1, 1.0f - ex2a(lB0));
        __stcs(o1 + c1, 1.0f - ex2a(lB1));
    }
    if (lane < NCOMB - 768) {                            // cols 768..780
        const int c = 768 + lane;
        const uint32_t w = __ldg(&d_ct.v[c]);
        const float2 a = *(const float2*)(vb + (w & 0xFFFFu));
        const float2 b = *(const float2*)(vb + (w >> 16));
        const float q0 = fmaf(-a.x, b.x, 1.0f);
        const float q1 = fmaf(-a.y, b.y, 1.0f);
        __stcs(o0 + c, 1.0f - ex2a(lg2a(q0) * inv));
        __stcs(o1 + c, 1.0f - ex2a(lg2a(q1) * inv));
    }
}

extern "C" void kernel_launch(void* const* d_in, const int* in_sizes, int n_in,
                              void* d_out, int out_size)
{
    const float* x   = (const float*)d_in[0];
    const float* lam = (const float*)d_in[1];
    float*       out = (float*)d_out;

    schweizer_kernel<<<NROWS / (WPB * RPW), 256>>>(x, lam, out);
}